// round 3
// baseline (speedup 1.0000x reference)
#include <cuda_runtime.h>
#include <math.h>

// ---------------------------------------------------------------------------
// 2-layer GCN (DGL norm='both') forward:
//   c_src = rsqrt(max(out_deg,1)), c_dst = rsqrt(max(in_deg,1))
//   h0 = (x @ W0) * c_src ; agg1[d] = sum_{e: dst=d} h0[src]; h1 = relu(agg1*c_dst + b0)
//   h2 = (h1 @ W1) * c_src ; agg2 -> h = agg2*c_dst + b1    (output part 1)
//   logits = relu(h) @ Wc + bc                               (output part 2)
//
// Strategy: build CSR-by-dst once per launch (int atomics only), warp-per-node
// register aggregation (no fp atomics), fp32 register-blocked SGEMMs with the
// c_src row-scale fused into the epilogue.
// ---------------------------------------------------------------------------

#define FIN  256
#define HID  128
#define NCLS 40
#define NMAX 100000
#define EMAX 1600000

// Scratch (static device allocations are the sanctioned workaround).
__device__ float g_h0[(size_t)NMAX * HID];     // 51.2 MB ping
__device__ float g_h1[(size_t)NMAX * HID];     // 51.2 MB pong
__device__ int   g_deg_out[NMAX];
__device__ int   g_deg_in[NMAX];
__device__ int   g_row_ptr[NMAX + 1];
__device__ int   g_cursor[NMAX];
__device__ int   g_src_sorted[EMAX];           // src ids grouped by dst
__device__ float g_csrc[NMAX];
__device__ float g_cdst[NMAX];

// ---------------------------------------------------------------------------
__global__ void zero_deg_kernel(int n) {
    int i = blockIdx.x * blockDim.x + threadIdx.x;
    if (i < n) { g_deg_out[i] = 0; g_deg_in[i] = 0; }
}

__global__ void hist_kernel(const int* __restrict__ src,
                            const int* __restrict__ dst, int e) {
    int i = blockIdx.x * blockDim.x + threadIdx.x;
    if (i < e) {
        atomicAdd(&g_deg_out[src[i]], 1);
        atomicAdd(&g_deg_in[dst[i]], 1);
    }
}

__global__ void norms_kernel(int n) {
    int i = blockIdx.x * blockDim.x + threadIdx.x;
    if (i < n) {
        g_csrc[i] = rsqrtf(fmaxf((float)g_deg_out[i], 1.0f));
        g_cdst[i] = rsqrtf(fmaxf((float)g_deg_in[i], 1.0f));
    }
}

// Single-block exclusive scan of g_deg_in -> g_row_ptr (+ cursor copy).
__global__ void scan_kernel(int n) {
    __shared__ int warp_sums[32];
    __shared__ int s_running;
    const int tid  = threadIdx.x;
    const int lane = tid & 31;
    const int wid  = tid >> 5;
    if (tid == 0) s_running = 0;
    __syncthreads();
    for (int base = 0; base < n; base += 1024) {
        int i = base + tid;
        int v = (i < n) ? g_deg_in[i] : 0;
        int x = v;
        #pragma unroll
        for (int off = 1; off < 32; off <<= 1) {
            int y = __shfl_up_sync(0xffffffffu, x, off);
            if (lane >= off) x += y;
        }
        if (lane == 31) warp_sums[wid] = x;
        __syncthreads();
        if (wid == 0) {
            int w = warp_sums[lane];
            #pragma unroll
            for (int off = 1; off < 32; off <<= 1) {
                int y = __shfl_up_sync(0xffffffffu, w, off);
                if (lane >= off) w += y;
            }
            warp_sums[lane] = w;  // inclusive across warps
        }
        __syncthreads();
        int run  = s_running;
        int excl = run + (x - v) + (wid > 0 ? warp_sums[wid - 1] : 0);
        if (i < n) { g_row_ptr[i] = excl; g_cursor[i] = excl; }
        __syncthreads();
        if (tid == 0) s_running = run + warp_sums[31];
        __syncthreads();
    }
    if (tid == 0) g_row_ptr[n] = s_running;
}

__global__ void build_csr_kernel(const int* __restrict__ src,
                                 const int* __restrict__ dst, int e) {
    int i = blockIdx.x * blockDim.x + threadIdx.x;
    if (i < e) {
        int pos = atomicAdd(&g_cursor[dst[i]], 1);
        g_src_sorted[pos] = src[i];
    }
}

// ---------------------------------------------------------------------------
// C[n x 128] = (A[n x K] @ W[K x 128]) * c_src[row]
// 128x128 tile, BK=16, 256 threads, 8x8 micro-tile per thread.
template <int K>
__global__ void __launch_bounds__(256)
gemm_csrc_kernel(const float* __restrict__ A, const float* __restrict__ W,
                 float* __restrict__ C, int n)
{
    __shared__ float As[16][129];  // padded: conflict-free transposed stores
    __shared__ float Bs[16][128];
    const int tid = threadIdx.x;
    const int tr  = tid >> 4;     // 0..15 (row group)
    const int tc  = tid & 15;     // 0..15 (col group)
    const int block_row = blockIdx.x * 128;

    float acc[8][8];
    #pragma unroll
    for (int i = 0; i < 8; ++i)
        #pragma unroll
        for (int j = 0; j < 8; ++j) acc[i][j] = 0.0f;

    const int ar  = tid >> 2;   // 0..63
    const int ac4 = tid & 3;    // 0..3  -> 16 cols as 4 float4
    const int br  = tid >> 5;   // 0..7
    const int bc4 = tid & 31;   // 0..31 -> 128 cols as 32 float4

    for (int k0 = 0; k0 < K; k0 += 16) {
        #pragma unroll
        for (int i = 0; i < 2; ++i) {
            int r = ar + i * 64;
            int grow = block_row + r;
            float4 v = make_float4(0.f, 0.f, 0.f, 0.f);
            if (grow < n)
                v = *reinterpret_cast<const float4*>(
                        &A[(size_t)grow * K + k0 + ac4 * 4]);
            As[ac4 * 4 + 0][r] = v.x;
            As[ac4 * 4 + 1][r] = v.y;
            As[ac4 * 4 + 2][r] = v.z;
            As[ac4 * 4 + 3][r] = v.w;
        }
        #pragma unroll
        for (int i = 0; i < 2; ++i) {
            int r = br + i * 8;
            float4 v = *reinterpret_cast<const float4*>(
                           &W[(size_t)(k0 + r) * 128 + bc4 * 4]);
            *reinterpret_cast<float4*>(&Bs[r][bc4 * 4]) = v;
        }
        __syncthreads();
        #pragma unroll
        for (int kk = 0; kk < 16; ++kk) {
            float ra[8], rb[8];
            #pragma unroll
            for (int i = 0; i < 8; ++i) ra[i] = As[kk][tr * 8 + i];
            #pragma unroll
            for (int j = 0; j < 8; ++j) rb[j] = Bs[kk][tc * 8 + j];
            #pragma unroll
            for (int i = 0; i < 8; ++i)
                #pragma unroll
                for (int j = 0; j < 8; ++j)
                    acc[i][j] = fmaf(ra[i], rb[j], acc[i][j]);
        }
        __syncthreads();
    }

    #pragma unroll
    for (int i = 0; i < 8; ++i) {
        int grow = block_row + tr * 8 + i;
        if (grow >= n) continue;
        float cs = g_csrc[grow];
        float* crow = &C[(size_t)grow * 128 + tc * 8];
        #pragma unroll
        for (int j = 0; j < 8; j += 4) {
            float4 v = make_float4(acc[i][j] * cs, acc[i][j + 1] * cs,
                                   acc[i][j + 2] * cs, acc[i][j + 3] * cs);
            *reinterpret_cast<float4*>(&crow[j]) = v;
        }
    }
}

// ---------------------------------------------------------------------------
// Warp-per-dst-node aggregation over CSR. lane owns one float4 (4 feats).
// out[d] = (sum_src hin[src]) * c_dst[d] + bias  [; relu]
template <bool RELU>
__global__ void agg_kernel(const float* __restrict__ hin,
                           const float* __restrict__ bias,
                           float* __restrict__ out, int n)
{
    int gw   = (blockIdx.x * blockDim.x + threadIdx.x) >> 5;
    int lane = threadIdx.x & 31;
    if (gw >= n) return;
    int p  = g_row_ptr[gw];
    int pe = g_row_ptr[gw + 1];
    const float4* hin4 = reinterpret_cast<const float4*>(hin);

    float4 a0 = make_float4(0.f, 0.f, 0.f, 0.f);
    float4 a1 = make_float4(0.f, 0.f, 0.f, 0.f);
    for (; p + 1 < pe; p += 2) {
        int s0 = __ldg(&g_src_sorted[p]);
        int s1 = __ldg(&g_src_sorted[p + 1]);
        float4 v0 = __ldg(&hin4[(size_t)s0 * 32 + lane]);
        float4 v1 = __ldg(&hin4[(size_t)s1 * 32 + lane]);
        a0.x += v0.x; a0.y += v0.y; a0.z += v0.z; a0.w += v0.w;
        a1.x += v1.x; a1.y += v1.y; a1.z += v1.z; a1.w += v1.w;
    }
    if (p < pe) {
        int s0 = __ldg(&g_src_sorted[p]);
        float4 v0 = __ldg(&hin4[(size_t)s0 * 32 + lane]);
        a0.x += v0.x; a0.y += v0.y; a0.z += v0.z; a0.w += v0.w;
    }
    float4 acc = make_float4(a0.x + a1.x, a0.y + a1.y, a0.z + a1.z, a0.w + a1.w);

    float  cd = g_cdst[gw];
    float4 b  = reinterpret_cast<const float4*>(bias)[lane];
    acc.x = fmaf(acc.x, cd, b.x);
    acc.y = fmaf(acc.y, cd, b.y);
    acc.z = fmaf(acc.z, cd, b.z);
    acc.w = fmaf(acc.w, cd, b.w);
    if (RELU) {
        acc.x = fmaxf(acc.x, 0.f); acc.y = fmaxf(acc.y, 0.f);
        acc.z = fmaxf(acc.z, 0.f); acc.w = fmaxf(acc.w, 0.f);
    }
    reinterpret_cast<float4*>(out)[(size_t)gw * 32 + lane] = acc;
}

// ---------------------------------------------------------------------------
// logits[n x 40] = relu(h[n x 128]) @ Wc + bc   (thread-per-node, Wc in smem)
__global__ void __launch_bounds__(256)
logits_kernel(const float* __restrict__ h, const float* __restrict__ Wc,
              const float* __restrict__ bc, float* __restrict__ out, int n)
{
    __shared__ float sW[HID * NCLS];
    __shared__ float sb[NCLS];
    for (int i = threadIdx.x; i < HID * NCLS; i += 256) sW[i] = Wc[i];
    if (threadIdx.x < NCLS) sb[threadIdx.x] = bc[threadIdx.x];
    __syncthreads();

    int node = blockIdx.x * blockDim.x + threadIdx.x;
    if (node >= n) return;

    float acc[NCLS];
    #pragma unroll
    for (int c = 0; c < NCLS; ++c) acc[c] = sb[c];

    const float4* h4 = reinterpret_cast<const float4*>(h + (size_t)node * HID);
    #pragma unroll 4
    for (int k4 = 0; k4 < 32; ++k4) {
        float4 v = h4[k4];
        v.x = fmaxf(v.x, 0.f); v.y = fmaxf(v.y, 0.f);
        v.z = fmaxf(v.z, 0.f); v.w = fmaxf(v.w, 0.f);
        const float* w0 = &sW[(k4 * 4 + 0) * NCLS];
        const float* w1 = w0 + NCLS;
        const float* w2 = w0 + 2 * NCLS;
        const float* w3 = w0 + 3 * NCLS;
        #pragma unroll
        for (int c = 0; c < NCLS; ++c)
            acc[c] += v.x * w0[c] + v.y * w1[c] + v.z * w2[c] + v.w * w3[c];
    }

    float4* o4 = reinterpret_cast<float4*>(&out[(size_t)node * NCLS]);
    #pragma unroll
    for (int c = 0; c < NCLS; c += 4)
        o4[c / 4] = make_float4(acc[c], acc[c + 1], acc[c + 2], acc[c + 3]);
}

// ---------------------------------------------------------------------------
extern "C" void kernel_launch(void* const* d_in, const int* in_sizes, int n_in,
                              void* d_out, int out_size)
{
    const float* x  = (const float*)d_in[0];
    const int*   src = (const int*)d_in[1];
    const int*   dst = (const int*)d_in[2];
    const float* W0 = (const float*)d_in[3];
    const float* b0 = (const float*)d_in[4];
    const float* W1 = (const float*)d_in[5];
    const float* b1 = (const float*)d_in[6];
    const float* Wc = (const float*)d_in[7];
    const float* bc = (const float*)d_in[8];

    const int n = in_sizes[0] / FIN;
    const int e = in_sizes[1];

    float* out    = (float*)d_out;
    float* h_out  = out;                        // N x 128 (layer-2 pre-relu h)
    float* logits = out + (size_t)n * HID;      // N x 40

    float *h0p = nullptr, *h1p = nullptr;
    cudaGetSymbolAddress((void**)&h0p, g_h0);
    cudaGetSymbolAddress((void**)&h1p, g_h1);

    const int tb = 256;
    // Degree norms + CSR-by-dst build (int atomics only)
    zero_deg_kernel<<<(n + tb - 1) / tb, tb>>>(n);
    hist_kernel<<<(e + tb - 1) / tb, tb>>>(src, dst, e);
    norms_kernel<<<(n + tb - 1) / tb, tb>>>(n);
    scan_kernel<<<1, 1024>>>(n);
    build_csr_kernel<<<(e + tb - 1) / tb, tb>>>(src, dst, e);

    // Layer 1: h0 = (x@W0)*c_src ; h1 = relu(agg(h0)*c_dst + b0)
    gemm_csrc_kernel<FIN><<<(n + 127) / 128, 256>>>(x, W0, h0p, n);
    agg_kernel<true><<<((size_t)n * 32 + tb - 1) / tb, tb>>>(h0p, b0, h1p, n);

    // Layer 2: h2 = (h1@W1)*c_src ; h = agg(h2)*c_dst + b1  -> d_out part 1
    gemm_csrc_kernel<HID><<<(n + 127) / 128, 256>>>(h1p, W1, h0p, n);
    agg_kernel<false><<<((size_t)n * 32 + tb - 1) / tb, tb>>>(h0p, b1, h_out, n);

    // Classifier: logits = relu(h)@Wc + bc  -> d_out part 2
    logits_kernel<<<(n + tb - 1) / tb, tb>>>(h_out, Wc, bc, logits, n);
}

// round 5
// speedup vs baseline: 1.4685x; 1.4685x over previous
#include <cuda_runtime.h>
#include <math.h>

// ---------------------------------------------------------------------------
// 2-layer GCN (DGL norm='both') forward.
//   h0 = (x @ W0) * c_src ; h1 = relu(agg(h0)*c_dst + b0)
//   h2 = (h1 @ W1) * c_src ; h = agg(h2)*c_dst + b1   (output part 1)
//   logits = relu(h) @ Wc + bc                         (output part 2)
// R4: fix B-tile staging in the tf32 GEMM (R3 only filled 512/2048 smem
//     elements -> garbage MMA operands, rel_err 28). uint4 staging now
//     covers all 128 cols x 16 k.
// ---------------------------------------------------------------------------

#define FIN  256
#define HID  128
#define NCLS 40
#define NMAX 100000
#define EMAX 1600000

__device__ float    g_h0[(size_t)NMAX * HID];
__device__ float    g_h1[(size_t)NMAX * HID];
__device__ int      g_deg_out[NMAX];
__device__ int      g_deg_in[NMAX];
__device__ int      g_row_ptr[NMAX + 1];
__device__ int      g_cursor[NMAX];
__device__ int      g_src_sorted[EMAX];
__device__ float    g_csrc[NMAX];
__device__ float    g_cdst[NMAX];
__device__ int      g_blk[128];
__device__ int      g_total;
__device__ unsigned g_W0t[128 * FIN];   // tf32, transposed [col][k]
__device__ unsigned g_W1t[128 * HID];

__device__ __forceinline__ unsigned f2tf32(float f) {
    unsigned u;
    asm("cvt.rna.tf32.f32 %0, %1;" : "=r"(u) : "f"(f));
    return u;
}

__device__ __forceinline__ void mma_tf32(float* c, const unsigned* a,
                                         const unsigned* b) {
    asm volatile(
        "mma.sync.aligned.m16n8k8.row.col.f32.tf32.tf32.f32 "
        "{%0,%1,%2,%3}, {%4,%5,%6,%7}, {%8,%9}, {%0,%1,%2,%3};"
        : "+f"(c[0]), "+f"(c[1]), "+f"(c[2]), "+f"(c[3])
        : "r"(a[0]), "r"(a[1]), "r"(a[2]), "r"(a[3]), "r"(b[0]), "r"(b[1]));
}

// ---------------------------------------------------------------------------
__global__ void zero_deg_kernel(int n) {
    int i = blockIdx.x * blockDim.x + threadIdx.x;
    if (i < n) { g_deg_out[i] = 0; g_deg_in[i] = 0; }
}

__global__ void hist_kernel(const int* __restrict__ src,
                            const int* __restrict__ dst, int e) {
    int i = blockIdx.x * blockDim.x + threadIdx.x;
    if (i < e) {
        atomicAdd(&g_deg_out[src[i]], 1);
        atomicAdd(&g_deg_in[dst[i]], 1);
    }
}

__global__ void norms_kernel(int n) {
    int i = blockIdx.x * blockDim.x + threadIdx.x;
    if (i < n) {
        g_csrc[i] = rsqrtf(fmaxf((float)g_deg_out[i], 1.0f));
        g_cdst[i] = rsqrtf(fmaxf((float)g_deg_in[i], 1.0f));
    }
}

// --- 3-phase parallel exclusive scan of g_deg_in -> g_row_ptr -------------
__global__ void scan_blocks_kernel(int n) {
    __shared__ int wsum[32];
    const int tid = threadIdx.x, lane = tid & 31, w = tid >> 5;
    int i = blockIdx.x * 1024 + tid;
    int v = (i < n) ? g_deg_in[i] : 0;
    int x = v;
    #pragma unroll
    for (int off = 1; off < 32; off <<= 1) {
        int y = __shfl_up_sync(0xffffffffu, x, off);
        if (lane >= off) x += y;
    }
    if (lane == 31) wsum[w] = x;
    __syncthreads();
    if (w == 0) {
        int s = wsum[lane];
        #pragma unroll
        for (int off = 1; off < 32; off <<= 1) {
            int y = __shfl_up_sync(0xffffffffu, s, off);
            if (lane >= off) s += y;
        }
        wsum[lane] = s;
    }
    __syncthreads();
    int excl = (x - v) + (w > 0 ? wsum[w - 1] : 0);
    if (i < n) g_row_ptr[i] = excl;
    if (tid == 1023) g_blk[blockIdx.x] = excl + v;  // block total
}

__global__ void scan_tops_kernel(int nb) {  // 1 block, 128 threads, nb<=128
    __shared__ int ws[4];
    const int tid = threadIdx.x, lane = tid & 31, w = tid >> 5;
    int v = (tid < nb) ? g_blk[tid] : 0;
    int x = v;
    #pragma unroll
    for (int off = 1; off < 32; off <<= 1) {
        int y = __shfl_up_sync(0xffffffffu, x, off);
        if (lane >= off) x += y;
    }
    if (lane == 31) ws[w] = x;
    __syncthreads();
    int add = 0;
    for (int j = 0; j < w; ++j) add += ws[j];
    int excl = add + x - v;
    if (tid < nb) g_blk[tid] = excl;
    if (tid == nb - 1) g_total = excl + v;
}

__global__ void scan_add_kernel(int n) {
    int i = blockIdx.x * blockDim.x + threadIdx.x;
    if (i < n) {
        int v = g_row_ptr[i] + g_blk[i >> 10];
        g_row_ptr[i] = v;
        g_cursor[i]  = v;
    }
    if (i == 0) g_row_ptr[n] = g_total;
}

__global__ void build_csr_kernel(const int* __restrict__ src,
                                 const int* __restrict__ dst, int e) {
    int i = blockIdx.x * blockDim.x + threadIdx.x;
    if (i < e) {
        int pos = atomicAdd(&g_cursor[dst[i]], 1);
        g_src_sorted[pos] = src[i];
    }
}

// --- convert W [K x 128] f32 -> tf32 transposed [128 x K] ------------------
__global__ void wconv_kernel(const float* __restrict__ W,
                             unsigned* __restrict__ Wt, int Kdim) {
    int i = blockIdx.x * blockDim.x + threadIdx.x;
    if (i < Kdim * 128) {
        int k = i >> 7, col = i & 127;
        Wt[col * Kdim + k] = f2tf32(W[i]);
    }
}

// ---------------------------------------------------------------------------
// C[n x 128] = (A[n x K] @ W[K x 128]) * c_src[row], tf32 tensor-core path.
// Block tile 128x128, 256 threads (8 warps = 4x2 of 32x64 warp tiles), BK=16.
template <int K>
__global__ void __launch_bounds__(256)
gemm_tf32_kernel(const float* __restrict__ A, const unsigned* __restrict__ Wt,
                 float* __restrict__ C, int n)
{
    __shared__ unsigned As[128][20];   // As[row][k], tf32 (stride 20: pad)
    __shared__ unsigned Bs[128][20];   // Bs[col][k], tf32
    const int tid  = threadIdx.x;
    const int lane = tid & 31;
    const int wid  = tid >> 5;
    const int wm   = (wid >> 1) * 32;  // warp row base
    const int wn   = (wid & 1) * 64;   // warp col base
    const int g    = lane >> 2;        // 0..7
    const int t    = lane & 3;         // 0..3
    const int block_row = blockIdx.x * 128;

    float acc[2][8][4];
    #pragma unroll
    for (int mi = 0; mi < 2; ++mi)
        #pragma unroll
        for (int ni = 0; ni < 8; ++ni)
            #pragma unroll
            for (int c = 0; c < 4; ++c) acc[mi][ni][c] = 0.0f;

    const int ar = tid >> 2;          // 0..63 (A staging row)
    const int ac = (tid & 3) * 4;     // 0,4,8,12

    for (int k0 = 0; k0 < K; k0 += 16) {
        // stage A: 128 rows x 16 k (float4 global loads, cvt.rna at store)
        #pragma unroll
        for (int i = 0; i < 2; ++i) {
            int row = ar + i * 64;
            int grow = block_row + row;
            float4 v = make_float4(0.f, 0.f, 0.f, 0.f);
            if (grow < n)
                v = *reinterpret_cast<const float4*>(
                        &A[(size_t)grow * K + k0 + ac]);
            As[row][ac + 0] = f2tf32(v.x);
            As[row][ac + 1] = f2tf32(v.y);
            As[row][ac + 2] = f2tf32(v.z);
            As[row][ac + 3] = f2tf32(v.w);
        }
        // stage B: 128 cols x 16 k (uint4 loads from pre-transposed tf32 Wt)
        // R4 FIX: covers the full 2048-element tile (R3 wrote only 512).
        #pragma unroll
        for (int i = 0; i < 2; ++i) {
            int col = (tid >> 2) + i * 64;   // 0..127
            int k   = (tid & 3) * 4;         // 0,4,8,12
            uint4 v = *reinterpret_cast<const uint4*>(
                          &Wt[(size_t)col * K + k0 + k]);
            Bs[col][k + 0] = v.x;
            Bs[col][k + 1] = v.y;
            Bs[col][k + 2] = v.z;
            Bs[col][k + 3] = v.w;
        }
        __syncthreads();

        #pragma unroll
        for (int kk = 0; kk < 16; kk += 8) {
            unsigned a[2][4], b[8][2];
            #pragma unroll
            for (int mi = 0; mi < 2; ++mi) {
                int r = wm + mi * 16 + g;
                a[mi][0] = As[r][kk + t];
                a[mi][1] = As[r + 8][kk + t];
                a[mi][2] = As[r][kk + t + 4];
                a[mi][3] = As[r + 8][kk + t + 4];
            }
            #pragma unroll
            for (int ni = 0; ni < 8; ++ni) {
                int c = wn + ni * 8 + g;
                b[ni][0] = Bs[c][kk + t];
                b[ni][1] = Bs[c][kk + t + 4];
            }
            #pragma unroll
            for (int mi = 0; mi < 2; ++mi)
                #pragma unroll
                for (int ni = 0; ni < 8; ++ni)
                    mma_tf32(acc[mi][ni], a[mi], b[ni]);
        }
        __syncthreads();
    }

    // epilogue: scale by c_src[row], float2 stores
    #pragma unroll
    for (int mi = 0; mi < 2; ++mi) {
        int r0 = block_row + wm + mi * 16 + g;
        int r1 = r0 + 8;
        float cs0 = (r0 < n) ? g_csrc[r0] : 0.f;
        float cs1 = (r1 < n) ? g_csrc[r1] : 0.f;
        #pragma unroll
        for (int ni = 0; ni < 8; ++ni) {
            int col = wn + ni * 8 + 2 * t;
            if (r0 < n) {
                float2 v = make_float2(acc[mi][ni][0] * cs0,
                                       acc[mi][ni][1] * cs0);
                *reinterpret_cast<float2*>(&C[(size_t)r0 * 128 + col]) = v;
            }
            if (r1 < n) {
                float2 v = make_float2(acc[mi][ni][2] * cs1,
                                       acc[mi][ni][3] * cs1);
                *reinterpret_cast<float2*>(&C[(size_t)r1 * 128 + col]) = v;
            }
        }
    }
}

// ---------------------------------------------------------------------------
// Warp-per-dst-node aggregation over CSR (fp32, no atomics).
template <bool RELU>
__global__ void agg_kernel(const float* __restrict__ hin,
                           const float* __restrict__ bias,
                           float* __restrict__ out, int n)
{
    int gw   = (blockIdx.x * blockDim.x + threadIdx.x) >> 5;
    int lane = threadIdx.x & 31;
    if (gw >= n) return;
    int p  = g_row_ptr[gw];
    int pe = g_row_ptr[gw + 1];
    const float4* hin4 = reinterpret_cast<const float4*>(hin);

    float4 a0 = make_float4(0.f, 0.f, 0.f, 0.f);
    float4 a1 = make_float4(0.f, 0.f, 0.f, 0.f);
    for (; p + 1 < pe; p += 2) {
        int s0 = __ldg(&g_src_sorted[p]);
        int s1 = __ldg(&g_src_sorted[p + 1]);
        float4 v0 = __ldg(&hin4[(size_t)s0 * 32 + lane]);
        float4 v1 = __ldg(&hin4[(size_t)s1 * 32 + lane]);
        a0.x += v0.x; a0.y += v0.y; a0.z += v0.z; a0.w += v0.w;
        a1.x += v1.x; a1.y += v1.y; a1.z += v1.z; a1.w += v1.w;
    }
    if (p < pe) {
        int s0 = __ldg(&g_src_sorted[p]);
        float4 v0 = __ldg(&hin4[(size_t)s0 * 32 + lane]);
        a0.x += v0.x; a0.y += v0.y; a0.z += v0.z; a0.w += v0.w;
    }
    float4 acc = make_float4(a0.x + a1.x, a0.y + a1.y, a0.z + a1.z, a0.w + a1.w);

    float  cd = g_cdst[gw];
    float4 b  = reinterpret_cast<const float4*>(bias)[lane];
    acc.x = fmaf(acc.x, cd, b.x);
    acc.y = fmaf(acc.y, cd, b.y);
    acc.z = fmaf(acc.z, cd, b.z);
    acc.w = fmaf(acc.w, cd, b.w);
    if (RELU) {
        acc.x = fmaxf(acc.x, 0.f); acc.y = fmaxf(acc.y, 0.f);
        acc.z = fmaxf(acc.z, 0.f); acc.w = fmaxf(acc.w, 0.f);
    }
    reinterpret_cast<float4*>(out)[(size_t)gw * 32 + lane] = acc;
}

// ---------------------------------------------------------------------------
__global__ void __launch_bounds__(256)
logits_kernel(const float* __restrict__ h, const float* __restrict__ Wc,
              const float* __restrict__ bc, float* __restrict__ out, int n)
{
    __shared__ float sW[HID * NCLS];
    __shared__ float sb[NCLS];
    for (int i = threadIdx.x; i < HID * NCLS; i += 256) sW[i] = Wc[i];
    if (threadIdx.x < NCLS) sb[threadIdx.x] = bc[threadIdx.x];
    __syncthreads();

    int node = blockIdx.x * blockDim.x + threadIdx.x;
    if (node >= n) return;

    float acc[NCLS];
    #pragma unroll
    for (int c = 0; c < NCLS; ++c) acc[c] = sb[c];

    const float4* h4 = reinterpret_cast<const float4*>(h + (size_t)node * HID);
    #pragma unroll 4
    for (int k4 = 0; k4 < 32; ++k4) {
        float4 v = h4[k4];
        v.x = fmaxf(v.x, 0.f); v.y = fmaxf(v.y, 0.f);
        v.z = fmaxf(v.z, 0.f); v.w = fmaxf(v.w, 0.f);
        const float* w0 = &sW[(k4 * 4 + 0) * NCLS];
        const float* w1 = w0 + NCLS;
        const float* w2 = w0 + 2 * NCLS;
        const float* w3 = w0 + 3 * NCLS;
        #pragma unroll
        for (int c = 0; c < NCLS; ++c)
            acc[c] += v.x * w0[c] + v.y * w1[c] + v.z * w2[c] + v.w * w3[c];
    }

    float4* o4 = reinterpret_cast<float4*>(&out[(size_t)node * NCLS]);
    #pragma unroll
    for (int c = 0; c < NCLS; c += 4)
        o4[c / 4] = make_float4(acc[c], acc[c + 1], acc[c + 2], acc[c + 3]);
}

// ---------------------------------------------------------------------------
extern "C" void kernel_launch(void* const* d_in, const int* in_sizes, int n_in,
                              void* d_out, int out_size)
{
    const float* x   = (const float*)d_in[0];
    const int*   src = (const int*)d_in[1];
    const int*   dst = (const int*)d_in[2];
    const float* W0  = (const float*)d_in[3];
    const float* b0  = (const float*)d_in[4];
    const float* W1  = (const float*)d_in[5];
    const float* b1  = (const float*)d_in[6];
    const float* Wc  = (const float*)d_in[7];
    const float* bc  = (const float*)d_in[8];

    const int n = in_sizes[0] / FIN;
    const int e = in_sizes[1];
    const int nb = (n + 1023) / 1024;

    float* out    = (float*)d_out;
    float* h_out  = out;                   // N x 128
    float* logits = out + (size_t)n * HID; // N x 40

    float *h0p, *h1p;
    unsigned *w0t, *w1t;
    cudaGetSymbolAddress((void**)&h0p, g_h0);
    cudaGetSymbolAddress((void**)&h1p, g_h1);
    cudaGetSymbolAddress((void**)&w0t, g_W0t);
    cudaGetSymbolAddress((void**)&w1t, g_W1t);

    const int tb = 256;

    // Weight conversion (independent)
    wconv_kernel<<<(FIN * 128 + tb - 1) / tb, tb>>>(W0, w0t, FIN);
    wconv_kernel<<<(HID * 128 + tb - 1) / tb, tb>>>(W1, w1t, HID);

    // Degree norms + CSR-by-dst (parallel 3-phase scan)
    zero_deg_kernel<<<(n + tb - 1) / tb, tb>>>(n);
    hist_kernel<<<(e + tb - 1) / tb, tb>>>(src, dst, e);
    norms_kernel<<<(n + tb - 1) / tb, tb>>>(n);
    scan_blocks_kernel<<<nb, 1024>>>(n);
    scan_tops_kernel<<<1, 128>>>(nb);
    scan_add_kernel<<<(n + tb - 1) / tb, tb>>>(n);
    build_csr_kernel<<<(e + tb - 1) / tb, tb>>>(src, dst, e);

    // Layer 1
    gemm_tf32_kernel<FIN><<<(n + 127) / 128, 256>>>(x, w0t, h0p, n);
    agg_kernel<true><<<((size_t)n * 32 + tb - 1) / tb, tb>>>(h0p, b0, h1p, n);

    // Layer 2
    gemm_tf32_kernel<HID><<<(n + 127) / 128, 256>>>(h1p, w1t, h0p, n);
    agg_kernel<false><<<((size_t)n * 32 + tb - 1) / tb, tb>>>(h0p, b1, h_out, n);

    // Classifier
    logits_kernel<<<(n + tb - 1) / tb, tb>>>(h_out, Wc, bc, logits, n);
}